// round 16
// baseline (speedup 1.0000x reference)
#include <cuda_runtime.h>
#include <cuda_bf16.h>
#include <math.h>

// Fixed shapes: cls_conv_out (4, 1029, 100, 100) fp32; rois (2000,4) int32.
// Only batch 3 used. Output (2000, 21, 1, 1) fp32.
#define KK       7
#define C1       21
#define NJL      49
#define H        100
#define W        100
#define HP       101
#define ROW_S    2124                 // HP*C1=2121 padded to mult of 4 (16B rows)
#define PLANE_S  (HP * ROW_S)
#define IN_BASE  (3 * 1029 * 10000)   // batch 3 offset
#define RPB      4                    // y-rows per block in kernel A
#define JL_SPLIT 25                   // planes 0..24 in chunk 0, 25..48 in chunk 1

// Integral image, transposed c-innermost: I[jl][y][x][c]; ~42 MB scratch.
__device__ float g_integral[(size_t)NJL * PLANE_S];

// ---------------------------------------------------------------------------
// Kernel A (R11 champion): block = (4 y-rows, jl-chunk), 21 warps = 1 channel.
// Each warp: 4 float4 loads, ONE 25-lane shuffle scan per row, scatter STS
// into the final transposed layout, 4 cp.async.bulk row stores, single wait.
// ---------------------------------------------------------------------------
__global__ void __launch_bounds__(672) build_xsum(const float* __restrict__ in,
                                                  int jl0) {
    const int ybase = RPB * blockIdx.x + 1;  // 1, 5, ..., 97
    const int jl    = jl0 + blockIdx.y;
    const int t     = threadIdx.x;
    const int c     = t >> 5;                // warp id == channel 0..20
    const int lane  = t & 31;

    __shared__ __align__(16) float smt[RPB][ROW_S];  // final rows: smt[r][x*21+c]

    // zero x=0 column (21 floats) and tail padding (3 floats) of each row buf
    if (t < 24) {
        const int idx = (t < C1) ? t : (2121 + t - C1);
        #pragma unroll
        for (int r = 0; r < RPB; r++) smt[r][idx] = 0.0f;
    }

    // --- loads: lane l holds float4 covering x = 4l..4l+3 of each row
    const float4* src4 = (const float4*)(in + IN_BASE
                        + (size_t)jl * (C1 * H * W) + (size_t)c * (H * W));
    float4 v[RPB];
    if (lane < 25) {
        #pragma unroll
        for (int r = 0; r < RPB; r++)
            v[r] = src4[(ybase - 1 + r) * (W / 4) + lane];
    }

    // --- per-row: in-thread scan of 4 + one shfl_up scan over lanes,
    // scatter-store into transposed layout (out position x+1).
    #pragma unroll
    for (int r = 0; r < RPB; r++) {
        float s0 = v[r].x;
        float s1 = s0 + v[r].y;
        float s2 = s1 + v[r].z;
        float s3 = s2 + v[r].w;
        float run = s3;
        #pragma unroll
        for (int d = 1; d < 32; d <<= 1) {
            float u = __shfl_up_sync(0xffffffffu, run, d);
            if (lane >= d) run += u;
        }
        const float off = run - s3;
        if (lane < 25) {
            float* sl = smt[r] + 84 * lane + C1 + c;
            sl[0]      = off + s0;
            sl[C1]     = off + s1;
            sl[2 * C1] = off + s2;
            sl[3 * C1] = off + s3;
        }
    }
    __syncthreads();

    // --- 4 bulk async row stores, single wait
    if (t == 0) {
        asm volatile("fence.proxy.async.shared::cta;" ::: "memory");
        float* gd = g_integral + ((size_t)jl * HP + ybase) * ROW_S;
        #pragma unroll
        for (int r = 0; r < RPB; r++) {
            unsigned sa;
            asm("{ .reg .u64 a; cvta.to.shared.u64 a, %1; cvt.u32.u64 %0, a; }"
                : "=r"(sa) : "l"(smt[r]));
            asm volatile(
                "cp.async.bulk.global.shared::cta.bulk_group [%0], [%1], %2;"
                :: "l"(gd + (size_t)r * ROW_S), "r"(sa), "r"(ROW_S * 4) : "memory");
        }
        asm volatile("cp.async.bulk.commit_group;" ::: "memory");
        asm volatile("cp.async.bulk.wait_group 0;" ::: "memory");
    }
}

// ---------------------------------------------------------------------------
// Kernel B: y-cumsum over float2 slots (1062/row); writes y=0 zero row then
// 100 dependent FADD2 steps, unroll 10 for load MLP.
// ---------------------------------------------------------------------------
__global__ void build_ysum(int jl0) {
    const int jl    = jl0 + blockIdx.y;
    const int slot2 = blockIdx.x * blockDim.x + threadIdx.x;
    if (slot2 >= ROW_S / 2) return;

    float2* p = (float2*)(g_integral + (size_t)jl * PLANE_S) + slot2;
    const int stride2 = ROW_S / 2;      // 1062

    float2 acc = make_float2(0.f, 0.f);
    p[0] = acc;                         // y = 0 row is zero
    #pragma unroll 10
    for (int y = 1; y <= H; y++) {
        float2 v = p[(size_t)y * stride2];
        acc.x += v.x; acc.y += v.y;
        p[(size_t)y * stride2] = acc;
    }
}

// ---------------------------------------------------------------------------
// Kernel C: TWO ROIs per block (halves the wave count; C is wave-bound).
// Threads 0..351 handle roi 2*bid, 352..703 roi 2*bid+1 (352 = 11 warps, so
// halves are warp-aligned). Per half: corner-base table in smem, register
// pre-reduction (16 jl-groups x 21 c), 21-thread final sum, warp softmax.
// ---------------------------------------------------------------------------
__global__ void __launch_bounds__(704) pool_softmax(const int* __restrict__ rois,
                                                    float* __restrict__ out) {
    const int t    = threadIdx.x;
    const int half = (t >= 352);
    const int t2   = t - 352 * half;
    const int roi  = 2 * blockIdx.x + half;

    __shared__ int   s_base[2][NJL * 4];
    __shared__ float s_part[2][336];
    __shared__ float s_avg[2][C1];

    const int4 r = ((const int4*)rois)[roi];   // ymin, xmin, ymax, xmax
    const int ys = (r.z - r.x) / KK;
    const int xs = (r.w - r.y) / KK;

    if (t2 < NJL * 4) {
        const int jl = t2 >> 2, corner = t2 & 3;
        const int j = jl / KK, l = jl - j * KK;
        const int y = ((corner & 1) ? (r.x + j * ys) : (r.x + j * ys + ys));
        const int x = ((corner & 2) ? (r.y + l * xs) : (r.y + l * xs + xs));
        s_base[half][t2] = jl * PLANE_S + y * ROW_S + x * C1;
    }
    __syncthreads();

    if (t2 < 336) {
        const int c   = t2 % C1;
        const int jl0 = t2 / C1;   // 0..15
        const float* P = g_integral + c;
        const int* bs = s_base[half];
        float part = 0.0f;
        #pragma unroll
        for (int jl = jl0; jl < NJL; jl += 16) {
            const int* bp = bs + 4 * jl;
            const float a = P[bp[0]];
            const float b = P[bp[1]];
            const float d = P[bp[2]];
            const float e = P[bp[3]];
            part += (a - b) - (d - e);
        }
        s_part[half][t2] = part;
    }
    __syncthreads();

    if (t2 < C1) {
        float acc = 0.0f;
        #pragma unroll
        for (int g = 0; g < 16; g++) acc += s_part[half][g * C1 + t2];
        s_avg[half][t2] = acc / (49.0f * (float)(ys * xs));
    }
    __syncthreads();

    if (t2 < 32) {
        const bool act = t2 < C1;
        float v = act ? s_avg[half][t2] : -INFINITY;
        float m = v;
        #pragma unroll
        for (int o = 16; o; o >>= 1) m = fmaxf(m, __shfl_xor_sync(0xffffffffu, m, o));
        float e = act ? expf(v - m) : 0.0f;
        float sum = e;
        #pragma unroll
        for (int o = 16; o; o >>= 1) sum += __shfl_xor_sync(0xffffffffu, sum, o);
        if (act) out[(size_t)roi * C1 + t2] = e / sum;
    }
}

// ---------------------------------------------------------------------------
// Forked-stream pipeline (captured into the graph as parallel branches):
//   legacy: A0 ─ e0 ─ B0 ─────────── wait(e1) ─ C
//   s1:          wait(e0) ─ A1 ─ B1 ─ e1
// A1 is ordered after A0 so B0 co-runs with A1 (B's L2 traffic hides under
// A's latency-bound execution).
// ---------------------------------------------------------------------------
extern "C" void kernel_launch(void* const* d_in, const int* in_sizes, int n_in,
                              void* d_out, int out_size) {
    const float* x    = (const float*)d_in[0];
    const int*   rois = (const int*)d_in[1];
    float*       out  = (float*)d_out;
    const int n_rois  = in_sizes[1] / 4;   // 2000

    static cudaStream_t s1;
    static cudaEvent_t  e0, e1;
    static int          init_done = 0;
    if (!init_done) {
        cudaStreamCreateWithFlags(&s1, cudaStreamNonBlocking);
        cudaEventCreateWithFlags(&e0, cudaEventDisableTiming);
        cudaEventCreateWithFlags(&e1, cudaEventDisableTiming);
        init_done = 1;
    }

    // chunk 0: planes 0..24 ; chunk 1: planes 25..48
    build_xsum<<<dim3(H / RPB, JL_SPLIT), 672>>>(x, 0);
    cudaEventRecord(e0, 0);
    cudaStreamWaitEvent(s1, e0, 0);
    build_xsum<<<dim3(H / RPB, NJL - JL_SPLIT), 672, 0, s1>>>(x, JL_SPLIT);

    build_ysum<<<dim3((ROW_S / 2 + 127) / 128, JL_SPLIT), 128>>>(0);
    build_ysum<<<dim3((ROW_S / 2 + 127) / 128, NJL - JL_SPLIT), 128, 0, s1>>>(JL_SPLIT);
    cudaEventRecord(e1, s1);
    cudaStreamWaitEvent(0, e1, 0);

    pool_softmax<<<n_rois / 2, 704>>>(rois, out);
}

// round 17
// speedup vs baseline: 1.1975x; 1.1975x over previous
#include <cuda_runtime.h>
#include <cuda_bf16.h>
#include <math.h>

// Fixed shapes: cls_conv_out (4, 1029, 100, 100) fp32; rois (2000,4) int32.
// Only batch 3 used. Output (2000, 21, 1, 1) fp32.
#define KK       7
#define C1       21
#define NJL      49
#define H        100
#define W        100
#define HP       101
#define ROW_S    2124                 // HP*C1=2121 padded to mult of 4 (16B rows)
#define PLANE_S  (HP * ROW_S)
#define IN_BASE  (3 * 1029 * 10000)   // batch 3 offset
#define RPB      4                    // y-rows per block in kernel A

// Integral image, transposed c-innermost: I[jl][y][x][c]; ~42 MB scratch.
__device__ float g_integral[(size_t)NJL * PLANE_S];

// ---------------------------------------------------------------------------
// Kernel A (R11 champion): block = (4 y-rows, jl), 21 warps = 1 channel.
// Each warp: 4 float4 loads, ONE 25-lane shuffle scan per row, scatter STS
// into the final transposed layout, 4 cp.async.bulk row stores, single wait.
// ---------------------------------------------------------------------------
__global__ void __launch_bounds__(672) build_xsum(const float* __restrict__ in) {
    const int ybase = RPB * blockIdx.x + 1;  // 1, 5, ..., 97
    const int jl    = blockIdx.y;            // 0..48
    const int t     = threadIdx.x;
    const int c     = t >> 5;                // warp id == channel 0..20
    const int lane  = t & 31;

    __shared__ __align__(16) float smt[RPB][ROW_S];  // final rows: smt[r][x*21+c]

    // zero x=0 column (21 floats) and tail padding (3 floats) of each row buf
    if (t < 24) {
        const int idx = (t < C1) ? t : (2121 + t - C1);
        #pragma unroll
        for (int r = 0; r < RPB; r++) smt[r][idx] = 0.0f;
    }

    // --- loads: lane l holds float4 covering x = 4l..4l+3 of each row
    const float4* src4 = (const float4*)(in + IN_BASE
                        + (size_t)jl * (C1 * H * W) + (size_t)c * (H * W));
    float4 v[RPB];
    if (lane < 25) {
        #pragma unroll
        for (int r = 0; r < RPB; r++)
            v[r] = src4[(ybase - 1 + r) * (W / 4) + lane];
    }

    // --- per-row: in-thread scan of 4 + one shfl_up scan over lanes,
    // scatter-store into transposed layout (out position x+1).
    #pragma unroll
    for (int r = 0; r < RPB; r++) {
        float s0 = v[r].x;
        float s1 = s0 + v[r].y;
        float s2 = s1 + v[r].z;
        float s3 = s2 + v[r].w;
        float run = s3;
        #pragma unroll
        for (int d = 1; d < 32; d <<= 1) {
            float u = __shfl_up_sync(0xffffffffu, run, d);
            if (lane >= d) run += u;
        }
        const float off = run - s3;
        if (lane < 25) {
            float* sl = smt[r] + 84 * lane + C1 + c;
            sl[0]      = off + s0;
            sl[C1]     = off + s1;
            sl[2 * C1] = off + s2;
            sl[3 * C1] = off + s3;
        }
    }
    __syncthreads();

    // --- 4 bulk async row stores, single wait
    if (t == 0) {
        asm volatile("fence.proxy.async.shared::cta;" ::: "memory");
        float* gd = g_integral + ((size_t)jl * HP + ybase) * ROW_S;
        #pragma unroll
        for (int r = 0; r < RPB; r++) {
            unsigned sa;
            asm("{ .reg .u64 a; cvta.to.shared.u64 a, %1; cvt.u32.u64 %0, a; }"
                : "=r"(sa) : "l"(smt[r]));
            asm volatile(
                "cp.async.bulk.global.shared::cta.bulk_group [%0], [%1], %2;"
                :: "l"(gd + (size_t)r * ROW_S), "r"(sa), "r"(ROW_S * 4) : "memory");
        }
        asm volatile("cp.async.bulk.commit_group;" ::: "memory");
        asm volatile("cp.async.bulk.wait_group 0;" ::: "memory");
    }
}

// ---------------------------------------------------------------------------
// Kernel B: y-cumsum, SCALAR slots (2121/row) -> 2x warps vs float2, same
// coalesced sector traffic; B is latency-bound on its dependent chain, so
// more resident warps is the lever. Unroll 10 for load MLP.
// ---------------------------------------------------------------------------
__global__ void build_ysum() {
    const int jl   = blockIdx.y;
    const int slot = blockIdx.x * blockDim.x + threadIdx.x;
    if (slot >= HP * C1) return;       // 2121 live slots (skip 3 pad lanes)

    float* p = g_integral + (size_t)jl * PLANE_S + slot;

    float acc = 0.0f;
    p[0] = acc;                         // y = 0 row is zero
    #pragma unroll 10
    for (int y = 1; y <= H; y++) {
        float v = p[(size_t)y * ROW_S];
        acc += v;
        p[(size_t)y * ROW_S] = acc;
    }
}

// ---------------------------------------------------------------------------
// Kernel C: TWO ROIs per block (halves wave count; C is wave/issue-bound).
// Threads 0..351 -> roi 2*bid, 352..703 -> roi 2*bid+1 (warp-aligned halves).
// Per half: corner-base table in smem, register pre-reduction
// (16 jl-groups x 21 c), 21-thread final sum, warp softmax.
// ---------------------------------------------------------------------------
__global__ void __launch_bounds__(704) pool_softmax(const int* __restrict__ rois,
                                                    float* __restrict__ out) {
    const int t    = threadIdx.x;
    const int half = (t >= 352);
    const int t2   = t - 352 * half;
    const int roi  = 2 * blockIdx.x + half;

    __shared__ int   s_base[2][NJL * 4];
    __shared__ float s_part[2][336];
    __shared__ float s_avg[2][C1];

    const int4 r = ((const int4*)rois)[roi];   // ymin, xmin, ymax, xmax
    const int ys = (r.z - r.x) / KK;
    const int xs = (r.w - r.y) / KK;

    if (t2 < NJL * 4) {
        const int jl = t2 >> 2, corner = t2 & 3;
        const int j = jl / KK, l = jl - j * KK;
        const int y = ((corner & 1) ? (r.x + j * ys) : (r.x + j * ys + ys));
        const int x = ((corner & 2) ? (r.y + l * xs) : (r.y + l * xs + xs));
        s_base[half][t2] = jl * PLANE_S + y * ROW_S + x * C1;
    }
    __syncthreads();

    if (t2 < 336) {
        const int c   = t2 % C1;
        const int jl0 = t2 / C1;   // 0..15
        const float* P = g_integral + c;
        const int* bs = s_base[half];
        float part = 0.0f;
        #pragma unroll
        for (int jl = jl0; jl < NJL; jl += 16) {
            const int* bp = bs + 4 * jl;
            const float a = P[bp[0]];
            const float b = P[bp[1]];
            const float d = P[bp[2]];
            const float e = P[bp[3]];
            part += (a - b) - (d - e);
        }
        s_part[half][t2] = part;
    }
    __syncthreads();

    if (t2 < C1) {
        float acc = 0.0f;
        #pragma unroll
        for (int g = 0; g < 16; g++) acc += s_part[half][g * C1 + t2];
        s_avg[half][t2] = acc / (49.0f * (float)(ys * xs));
    }
    __syncthreads();

    if (t2 < 32) {
        const bool act = t2 < C1;
        float v = act ? s_avg[half][t2] : -INFINITY;
        float m = v;
        #pragma unroll
        for (int o = 16; o; o >>= 1) m = fmaxf(m, __shfl_xor_sync(0xffffffffu, m, o));
        float e = act ? expf(v - m) : 0.0f;
        float sum = e;
        #pragma unroll
        for (int o = 16; o; o >>= 1) sum += __shfl_xor_sync(0xffffffffu, sum, o);
        if (act) out[(size_t)roi * C1 + t2] = e / sum;
    }
}

// ---------------------------------------------------------------------------
extern "C" void kernel_launch(void* const* d_in, const int* in_sizes, int n_in,
                              void* d_out, int out_size) {
    const float* x    = (const float*)d_in[0];
    const int*   rois = (const int*)d_in[1];
    float*       out  = (float*)d_out;
    const int n_rois  = in_sizes[1] / 4;   // 2000

    dim3 gA(H / RPB, NJL);                  // 25 x 49
    build_xsum<<<gA, 672>>>(x);

    dim3 gB((HP * C1 + 127) / 128, NJL);    // 17 x 49 = 833 blocks
    build_ysum<<<gB, 128>>>();

    pool_softmax<<<n_rois / 2, 704>>>(rois, out);
}